// round 15
// baseline (speedup 1.0000x reference)
#include <cuda_runtime.h>
#include <cuda_bf16.h>
#include <cuda_fp16.h>
#include <math.h>
#include <cstdint>

#define NB 8
#define SEQ 512
#define DM 1024
#define NH 16
#define HDIM 64

// ---------------- scratch (static __device__: allocation-guard safe) -------
__device__ float g_pos[1024 * 64];            // relative positional table (fp32)
__device__ float g_E[16 * 1024];              // (r_w - r_r) . pos[j]
__device__ __nv_bfloat16 g_xhi[4096 * 1024];  // x split hi (K operand)
__device__ __nv_bfloat16 g_xlo[4096 * 1024];  // x split lo
__device__ __nv_bfloat16 g_whi[2048 * 1024];  // Wqv^T split hi  [n][k]
__device__ __nv_bfloat16 g_wlo[2048 * 1024];  // Wqv^T split lo
__device__ __nv_bfloat16 g_push[1024 * 64];   // pos split hi
__device__ __nv_bfloat16 g_posl[1024 * 64];   // pos split lo
__device__ __nv_bfloat16 g_qhi[4096 * 1024];  // A1 = q + r_r split hi
__device__ __nv_bfloat16 g_qlo[4096 * 1024];  // A1 split lo
__device__ unsigned short g_vf16[4096 * 1024];// V as fp16

// ---------------- helpers ---------------------------------------------------
__device__ __forceinline__ uint32_t smem_u32(const void* p) {
    uint32_t a;
    asm("{ .reg .u64 t; cvta.to.shared.u64 t, %1; cvt.u32.u64 %0, t; }" : "=r"(a) : "l"(p));
    return a;
}
__device__ __forceinline__ void ldmatrix_x4(uint32_t* r, uint32_t addr) {
    asm volatile("ldmatrix.sync.aligned.m8n8.x4.shared.b16 {%0,%1,%2,%3}, [%4];"
                 : "=r"(r[0]), "=r"(r[1]), "=r"(r[2]), "=r"(r[3]) : "r"(addr));
}
__device__ __forceinline__ void ldmatrix_x4_t(uint32_t* r, uint32_t addr) {
    asm volatile("ldmatrix.sync.aligned.m8n8.x4.trans.shared.b16 {%0,%1,%2,%3}, [%4];"
                 : "=r"(r[0]), "=r"(r[1]), "=r"(r[2]), "=r"(r[3]) : "r"(addr));
}
__device__ __forceinline__ void mma_bf16(float* c, const uint32_t* a, const uint32_t* b) {
    asm volatile("mma.sync.aligned.m16n8k16.row.col.f32.bf16.bf16.f32 "
                 "{%0,%1,%2,%3}, {%4,%5,%6,%7}, {%8,%9}, {%0,%1,%2,%3};"
                 : "+f"(c[0]), "+f"(c[1]), "+f"(c[2]), "+f"(c[3])
                 : "r"(a[0]), "r"(a[1]), "r"(a[2]), "r"(a[3]), "r"(b[0]), "r"(b[1]));
}
__device__ __forceinline__ void mma_f16(float* c, const uint32_t* a, const uint32_t* b) {
    asm volatile("mma.sync.aligned.m16n8k16.row.col.f32.f16.f16.f32 "
                 "{%0,%1,%2,%3}, {%4,%5,%6,%7}, {%8,%9}, {%0,%1,%2,%3};"
                 : "+f"(c[0]), "+f"(c[1]), "+f"(c[2]), "+f"(c[3])
                 : "r"(a[0]), "r"(a[1]), "r"(a[2]), "r"(a[3]), "r"(b[0]), "r"(b[1]));
}
__device__ __forceinline__ void cp_async16(uint32_t saddr, const void* gaddr) {
    asm volatile("cp.async.cg.shared.global [%0], [%1], 16;" ::"r"(saddr), "l"(gaddr));
}
#define CP_COMMIT() asm volatile("cp.async.commit_group;" ::: "memory")
#define CP_WAIT(N) asm volatile("cp.async.wait_group %0;" ::"n"(N) : "memory")

__device__ __forceinline__ uint32_t pack2(__nv_bfloat16 lo, __nv_bfloat16 hi) {
    uint16_t a = *(uint16_t*)&lo, b = *(uint16_t*)&hi;
    return (uint32_t)a | ((uint32_t)b << 16);
}
__device__ __forceinline__ void store_split(__nv_bfloat16* hi, __nv_bfloat16* lo,
                                            size_t idx, float a, float b) {
    __nv_bfloat16 ha = __float2bfloat16(a), hb = __float2bfloat16(b);
    __nv_bfloat16 la = __float2bfloat16(a - __bfloat162float(ha));
    __nv_bfloat16 lb = __float2bfloat16(b - __bfloat162float(hb));
    *(uint32_t*)(hi + idx) = pack2(ha, hb);
    *(uint32_t*)(lo + idx) = pack2(la, lb);
}

// ---------------------------------------------------------------------------
// prep kernels (unchanged from R14)
// ---------------------------------------------------------------------------
__global__ void k_cvt_x(const float* __restrict__ x) {
    int i = (blockIdx.x * blockDim.x + threadIdx.x) * 4;
    float4 v = *(const float4*)(x + i);
    float a[4] = {v.x, v.y, v.z, v.w};
    __nv_bfloat16 h[4], l[4];
#pragma unroll
    for (int j = 0; j < 4; j++) {
        h[j] = __float2bfloat16(a[j]);
        l[j] = __float2bfloat16(a[j] - __bfloat162float(h[j]));
    }
    *(uint2*)(g_xhi + i) = *(uint2*)h;
    *(uint2*)(g_xlo + i) = *(uint2*)l;
}

__global__ void k_cvt_w(const float* __restrict__ W) {
    __shared__ float t[32][33];
    int tx = threadIdx.x, ty = threadIdx.y;
    int n0 = blockIdx.x * 32, k0 = blockIdx.y * 32;
#pragma unroll
    for (int i = 0; i < 4; i++)
        t[ty + i * 8][tx] = W[(size_t)(k0 + ty + i * 8) * 2048 + n0 + tx];
    __syncthreads();
#pragma unroll
    for (int i = 0; i < 4; i++) {
        int n = n0 + ty + i * 8;
        float v = t[tx][ty + i * 8];
        __nv_bfloat16 h = __float2bfloat16(v);
        g_whi[(size_t)n * 1024 + k0 + tx] = h;
        g_wlo[(size_t)n * 1024 + k0 + tx] = __float2bfloat16(v - __bfloat162float(h));
    }
}

__global__ void k_pos() {
    int idx = blockIdx.x * blockDim.x + threadIdx.x;
    if (idx >= 1024 * 64) return;
    int j = idx >> 6;
    int i = idx & 63;
    const float C = -logf(10000.0f) / 31.0f;
    int ii = (i < 32) ? i : (i - 32);
    float freq = expf((float)ii * C);
    float arg = (float)(j - 512) * freq;
    float v = (i < 32) ? sinf(arg) : cosf(arg);
    g_pos[idx] = v;
    __nv_bfloat16 h = __float2bfloat16(v);
    g_push[idx] = h;
    g_posl[idx] = __float2bfloat16(v - __bfloat162float(h));
}

__global__ void k_E(const float* __restrict__ rr, const float* __restrict__ rw) {
    int j = blockIdx.x * 128 + threadIdx.x;
    int h = blockIdx.y;
    const float4* pp = (const float4*)(g_pos + (size_t)j * 64);
    const float4* pr = (const float4*)(rr + h * 64);
    const float4* pw = (const float4*)(rw + h * 64);
    float s = 0.f;
#pragma unroll
    for (int d = 0; d < 16; d++) {
        float4 p = pp[d], a = pw[d], bq = pr[d];
        s += (a.x - bq.x) * p.x + (a.y - bq.y) * p.y +
             (a.z - bq.z) * p.z + (a.w - bq.w) * p.w;
    }
    g_E[h * 1024 + j] = s;
}

// ---------------------------------------------------------------------------
// qv = x @ Wqv (unchanged proven R14 kernel)
// ---------------------------------------------------------------------------
#define RS 72
#define TILE_B 18432
#define STAGE_B 73728

__global__ void __launch_bounds__(256) k_mm(const float* __restrict__ rr) {
    extern __shared__ __nv_bfloat16 smb[];
    const uint32_t sb = smem_u32(smb);
    const int tid = threadIdx.x;
    const int wid = tid >> 5, lane = tid & 31;
    const int m0 = blockIdx.y * 128, n0 = blockIdx.x * 128;

    const __nv_bfloat16* src0 = g_xhi + (size_t)m0 * 1024;
    const __nv_bfloat16* src1 = g_xlo + (size_t)m0 * 1024;
    const __nv_bfloat16* src2 = g_whi + (size_t)n0 * 1024;
    const __nv_bfloat16* src3 = g_wlo + (size_t)n0 * 1024;

    const int p_row = tid >> 1;
    const int p_c0 = (tid & 1) * 2;

    const int wm = wid >> 1, wn = wid & 1;
    const int m_base = wm * 32, n_base = wn * 64;
    const int lr = lane & 7, q = lane >> 3;

    float acc[2][8][4];
#pragma unroll
    for (int i = 0; i < 2; i++)
#pragma unroll
        for (int j = 0; j < 8; j++)
#pragma unroll
            for (int k = 0; k < 4; k++) acc[i][j][k] = 0.f;

#define PREFETCH(KT, STAGE)                                                              \
    do {                                                                                 \
        const int _k0 = (KT) * 32;                                                       \
        const uint32_t _stg = sb + (STAGE) * STAGE_B;                                    \
        const uint32_t _soff = (uint32_t)(p_row * RS) * 2 + p_c0 * 16;                   \
        const size_t _goff = (size_t)p_row * 1024 + _k0 + p_c0 * 8;                      \
        cp_async16(_stg + _soff, src0 + _goff);                                          \
        cp_async16(_stg + _soff + 16, src0 + _goff + 8);                                 \
        cp_async16(_stg + TILE_B + _soff, src1 + _goff);                                 \
        cp_async16(_stg + TILE_B + _soff + 16, src1 + _goff + 8);                        \
        cp_async16(_stg + 2 * TILE_B + _soff, src2 + _goff);                             \
        cp_async16(_stg + 2 * TILE_B + _soff + 16, src2 + _goff + 8);                    \
        cp_async16(_stg + 3 * TILE_B + _soff, src3 + _goff);                             \
        cp_async16(_stg + 3 * TILE_B + _soff + 16, src3 + _goff + 8);                    \
    } while (0)

    PREFETCH(0, 0);
    CP_COMMIT();
    PREFETCH(1, 1);
    CP_COMMIT();

    for (int kt = 0; kt < 32; kt++) {
        if (kt + 2 < 32) {
            const int st2 = (kt + 2) % 3;
            PREFETCH(kt + 2, st2);
        }
        CP_COMMIT();
        CP_WAIT(2);
        __syncthreads();

        const uint32_t stg = sb + (kt % 3) * STAGE_B;
        const uint32_t bAh = stg, bAl = stg + TILE_B;
        const uint32_t bBh = stg + 2 * TILE_B, bBl = stg + 3 * TILE_B;

#pragma unroll
        for (int kk = 0; kk < 32; kk += 16) {
            uint32_t bh[8][2], bl[8][2];
#pragma unroll
            for (int nb = 0; nb < 4; nb++) {
                int rown = n_base + nb * 16 + ((q >> 1) * 8) + lr;
                int colk = kk + (q & 1) * 8;
                uint32_t off = (uint32_t)(rown * RS + colk) * 2;
                uint32_t r4[4];
                ldmatrix_x4(r4, bBh + off);
                bh[nb * 2][0] = r4[0]; bh[nb * 2][1] = r4[1];
                bh[nb * 2 + 1][0] = r4[2]; bh[nb * 2 + 1][1] = r4[3];
                ldmatrix_x4(r4, bBl + off);
                bl[nb * 2][0] = r4[0]; bl[nb * 2][1] = r4[1];
                bl[nb * 2 + 1][0] = r4[2]; bl[nb * 2 + 1][1] = r4[3];
            }
#pragma unroll
            for (int mb = 0; mb < 2; mb++) {
                int rowm = m_base + mb * 16 + ((q & 1) * 8) + lr;
                int colk = kk + (q >> 1) * 8;
                uint32_t off = (uint32_t)(rowm * RS + colk) * 2;
                uint32_t ah[4], al[4];
                ldmatrix_x4(ah, bAh + off);
                ldmatrix_x4(al, bAl + off);
#pragma unroll
                for (int nb = 0; nb < 8; nb++) {
                    mma_bf16(acc[mb][nb], ah, bh[nb]);
                    mma_bf16(acc[mb][nb], ah, bl[nb]);
                    mma_bf16(acc[mb][nb], al, bh[nb]);
                }
            }
        }
        __syncthreads();
    }

#pragma unroll
    for (int mb = 0; mb < 2; mb++) {
        int row0 = m0 + m_base + mb * 16 + (lane >> 2);
#pragma unroll
        for (int nb = 0; nb < 8; nb++) {
            int col = n0 + n_base + nb * 8 + (lane & 3) * 2;
            if (col < 1024) {
                float2 rb = *(const float2*)(rr + col);
                store_split(g_qhi, g_qlo, (size_t)row0 * 1024 + col,
                            acc[mb][nb][0] + rb.x, acc[mb][nb][1] + rb.y);
                store_split(g_qhi, g_qlo, (size_t)(row0 + 8) * 1024 + col,
                            acc[mb][nb][2] + rb.x, acc[mb][nb][3] + rb.y);
            } else {
                int c2 = col - 1024;
                __half2 p0 = __floats2half2_rn(acc[mb][nb][0], acc[mb][nb][1]);
                __half2 p1 = __floats2half2_rn(acc[mb][nb][2], acc[mb][nb][3]);
                *(uint32_t*)(g_vf16 + (size_t)row0 * 1024 + c2) = *(uint32_t*)&p0;
                *(uint32_t*)(g_vf16 + (size_t)(row0 + 8) * 1024 + c2) = *(uint32_t*)&p1;
            }
        }
    }
#undef PREFETCH
}

// ---------------------------------------------------------------------------
// Warp-specialized tensor-core attention (256 threads).
// Warps 0-3 (main): PV(kt-1) -> AC(kt) -> combine/softmax. Warps 4-7 (gw):
// staging issue (K(kt+1), pos(kt+3), mk) and g_block(kt+2) concurrent with
// main's P-convert + V-load latency. 2 barriers per tile.
// Smem: KV 3-ring 3x18432 | pos ping-pong 2x18432 | Gs 34816 | P fp16 | mk[2][64]
// ---------------------------------------------------------------------------
#define SM_KV(i)   ((i) * 18432)            // hi +0, lo +9216; V fp16 in hi half
#define SM_POS(p)  (55296 + (p) * 18432)    // hi +0, lo +9216
#define SM_GS      92160
#define SM_PH      126976
#define SM_MK      136192                   // mk[2][64] floats
#define SM_ATTN_TOT 136704

__device__ __forceinline__ void g_block(uint32_t sb, float* Gs,
                                        const uint32_t (&a1h)[4][4],
                                        const uint32_t (&a1l)[4][4],
                                        int wg, int lane, int blk,
                                        const float* __restrict__ Eh, int base0) {
    const int lr = lane & 7, qd = lane >> 3;
    const int rowBg = (qd >> 1) * 8 + lr;
    const int rg = 16 * wg + (lane >> 2);
    const int cgl = (lane & 3) * 2;
    const int slot = blk & 1;
    const uint32_t posb = sb + SM_POS(blk & 1);   // pos(blk) lives in PB(blk&1)... see schedule
#pragma unroll
    for (int nb = 0; nb < 4; nb++) {
        float g0[4] = {0.f, 0.f, 0.f, 0.f}, g1[4] = {0.f, 0.f, 0.f, 0.f};
#pragma unroll
        for (int ks = 0; ks < 4; ks++) {
            int colB = ks * 16 + (qd & 1) * 8;
            uint32_t off = (uint32_t)((nb * 16 + rowBg) * RS + colB) * 2;
            uint32_t bh4[4], bl4[4];
            ldmatrix_x4(bh4, posb + off);
            ldmatrix_x4(bl4, posb + 9216 + off);
            mma_bf16(g0, a1h[ks], bh4);
            mma_bf16(g0, a1h[ks], bl4);
            mma_bf16(g0, a1l[ks], bh4);
            mma_bf16(g1, a1h[ks], bh4 + 2);
            mma_bf16(g1, a1h[ks], bl4 + 2);
            mma_bf16(g1, a1l[ks], bh4 + 2);
        }
        int cg = nb * 16 + cgl;
        int gi = base0 + blk * 64 + cg;
        float e0 = Eh[min(gi, 1023)];
        float e1 = Eh[min(gi + 1, 1023)];
        float e8 = Eh[min(gi + 8, 1023)];
        float e9 = Eh[min(gi + 9, 1023)];
        int bq = rg * 136 + slot * 68;
        *(float2*)&Gs[bq + cg] = make_float2(g0[0] + e0, g0[1] + e1);
        *(float2*)&Gs[bq + 8 * 136 + cg] = make_float2(g0[2] + e0, g0[3] + e1);
        *(float2*)&Gs[bq + cg + 8] = make_float2(g1[0] + e8, g1[1] + e9);
        *(float2*)&Gs[bq + 8 * 136 + cg + 8] = make_float2(g1[2] + e8, g1[3] + e9);
    }
}

__global__ void __launch_bounds__(256) k_attn(const int* __restrict__ mask,
                                              float* __restrict__ out) {
    extern __shared__ char smc[];
    const uint32_t sb = smem_u32(smc);
    float* Gs = (float*)(smc + SM_GS);
    float* mkb = (float*)(smc + SM_MK);     // [2][64]

    const int tid = threadIdx.x;
    const int wid = tid >> 5, lane = tid & 31;
    const int wg = wid & 3;
    const bool is_main = wid < 4;
    const int tidg = tid & 127;             // index within half
    const int lr = lane & 7, qd = lane >> 3;
    const int bh = blockIdx.y;
    const int b = bh >> 4, h = bh & 15;
    const int q0 = blockIdx.x * 64;
    const int base0 = 449 - q0;
    const float* Eh = g_E + h * 1024;

    // ---- prologue: stage A1 splits into (future) Gs region (all threads) ----
    for (int i = tid; i < 512; i += 256) {
        int row = i >> 3, c = i & 7;
        size_t g = (size_t)(b * SEQ + q0 + row) * 1024 + h * 64 + c * 8;
        *(uint4*)(smc + SM_GS + (row * RS + c * 8) * 2) = *(const uint4*)(g_qhi + g);
        *(uint4*)(smc + SM_GS + 9216 + (row * RS + c * 8) * 2) = *(const uint4*)(g_qlo + g);
    }
    if (tid < 64) mkb[tid] = (float)mask[b * SEQ + tid];   // mk[0]
    __syncthreads();

    // all 8 warps load A1 fragments for their row group wg
    uint32_t a1h[4][4], a1l[4][4];
    {
        int rowA = 16 * wg + (qd & 1) * 8 + lr;
#pragma unroll
        for (int ks = 0; ks < 4; ks++) {
            int colA = ks * 16 + (qd >> 1) * 8;
            ldmatrix_x4(a1h[ks], sb + SM_GS + (uint32_t)(rowA * RS + colA) * 2);
            ldmatrix_x4(a1l[ks], sb + SM_GS + 9216 + (uint32_t)(rowA * RS + colA) * 2);
        }
    }

    // prologue staging: main -> K(0); gw -> pos(0)->PB0, pos(1)->PB1
    if (is_main) {
        for (int i = tidg; i < 512; i += 128) {
            int row = i >> 3, c = i & 7;
            size_t g = (size_t)(b * SEQ + row) * 1024 + h * 64 + c * 8;
            uint32_t d = sb + SM_KV(0) + (row * RS + c * 8) * 2;
            cp_async16(d, g_xhi + g);
            cp_async16(d + 9216, g_xlo + g);
        }
        CP_COMMIT();
        CP_WAIT(0);
    } else {
#pragma unroll
        for (int bi = 0; bi < 2; bi++) {
            int pbase = base0 + 64 * bi;
            for (int i = tidg; i < 512; i += 128) {
                int row = i >> 3, c = i & 7;
                int j = pbase + row; if (j > 1023) j = 1023;
                size_t g = (size_t)j * 64 + c * 8;
                uint32_t d = sb + SM_POS(bi) + (row * RS + c * 8) * 2;
                cp_async16(d, g_push + g);
                cp_async16(d + 9216, g_posl + g);
            }
        }
        CP_COMMIT();
        CP_WAIT(0);
    }
    __syncthreads();   // A1 frags loaded by all; pos0/1 + K0 published

    if (!is_main) {
        g_block(sb, Gs, a1h, a1l, wg, lane, 0, Eh, base0);
        g_block(sb, Gs, a1h, a1l, wg, lane, 1, Eh, base0);
        // stage pos(2) -> PB0 (after own g_block(0) read)
        {
            int pbase = base0 + 128;
            for (int i = tidg; i < 512; i += 128) {
                int row = i >> 3, c = i & 7;
                int j = pbase + row; if (j > 1023) j = 1023;
                size_t g = (size_t)j * 64 + c * 8;
                uint32_t d = sb + SM_POS(0) + (row * RS + c * 8) * 2;
                cp_async16(d, g_push + g);
                cp_async16(d + 9216, g_posl + g);
            }
            CP_COMMIT();   // retired at kt=0 window2 WAIT(1)
        }
    }
    __syncthreads();   // Gs blocks 0,1 + K(0) published to all

    float m0 = -1e30f, m1 = -1e30f, l0 = 0.f, l1 = 0.f;
    float O[8][4];
#pragma unroll
    for (int i = 0; i < 8; i++)
#pragma unroll
        for (int j = 0; j < 4; j++) O[i][j] = 0.f;

    const int rq0 = 16 * wg + (lane >> 2);
    const int rq1 = rq0 + 8;
    float acc[8][4];

    for (int kt = 0; kt < 8; kt++) {
        const int k0t = kt * 64;

        // ================= window 1 =================
        if (is_main) {
            // ---- PV(kt-1) ----
            if (kt > 0) {
                const uint32_t vb = sb + SM_KV((kt - 1) % 3);
                int rowP = 16 * wg + (qd & 1) * 8 + lr;
#pragma unroll
                for (int ks = 0; ks < 4; ks++) {
                    int colP = ks * 16 + (qd >> 1) * 8;
                    uint32_t ap[4];
                    ldmatrix_x4(ap, sb + SM_PH + (uint32_t)(rowP * RS + colP) * 2);
                    int rowV = ks * 16 + (qd & 1) * 8 + lr;
#pragma unroll
                    for (int dt = 0; dt < 4; dt++) {
                        int colV = dt * 16 + (qd >> 1) * 8;
                        uint32_t off = (uint32_t)(rowV * RS + colV) * 2;
                        uint32_t vh[4];
                        ldmatrix_x4_t(vh, vb + off);
                        mma_f16(O[dt * 2], ap, vh);
                        mma_f16(O[dt * 2 + 1], ap, vh + 2);
                    }
                }
            }
            // ---- AC(kt) ----
            const uint32_t kb = sb + SM_KV(kt % 3);
#pragma unroll
            for (int i = 0; i < 8; i++)
#pragma unroll
                for (int j = 0; j < 4; j++) acc[i][j] = 0.f;
            {
                int rowBg = (qd >> 1) * 8 + lr;
#pragma unroll
                for (int nb = 0; nb < 4; nb++) {
#pragma unroll
                    for (int ks = 0; ks < 4; ks++) {
                        int colB = ks * 16 + (qd & 1) * 8;
                        uint32_t off = (uint32_t)((nb * 16 + rowBg) * RS + colB) * 2;
                        uint32_t kh4[4], kl4[4];
                        ldmatrix_x4(kh4, kb + off);
                        ldmatrix_x4(kl4, kb + 9216 + off);
                        mma_bf16(acc[nb * 2], a1h[ks], kh4);
                        mma_bf16(acc[nb * 2], a1h[ks], kl4);
                        mma_bf16(acc[nb * 2], a1l[ks], kh4);
                        mma_bf16(acc[nb * 2 + 1], a1h[ks], kh4 + 2);
                        mma_bf16(acc[nb * 2 + 1], a1h[ks], kl4 + 2);
                        mma_bf16(acc[nb * 2 + 1], a1l[ks], kh4 + 2);
                    }
                }
            }
            // ---- combine + online softmax ----
            const float* mk = mkb + (kt & 1) * 64;
            float rmax0 = -1e30f, rmax1 = -1e30f;
#pragma unroll
            for (int nt = 0; nt < 8; nt++) {
                int c0 = nt * 8 + (lane & 3) * 2;
#pragma unroll
                for (int e = 0; e < 4; e++) {
                    int q = (e < 2) ? rq0 : rq1;
                    int k = c0 + (e & 1);
                    int gg = 64 * kt + k - q + 63;
                    int slot = (gg >> 6) & 1;
                    int col = gg & 63;
                    float s = acc[nt][e] + Gs[q * 136 + slot * 68 + col];
                    float mv = mk[k];
                    s = s * mv - (1.f - mv) * 1e8f;
                    acc[nt][e] = s;
                    if (e < 2) rmax0 = fmaxf(rmax0, s); else rmax1 = fmaxf(rmax1, s);
                }
            }
            rmax0 = fmaxf(rmax0, __shfl_xor_sync(0xffffffffu, rmax0, 1));
            rmax0 = fmaxf(rmax0, __shfl_xor_sync(0xffffffffu, rmax0, 2));
            rmax1 = fmaxf(rmax1, __shfl_xor_sync(0xffffffffu, rmax1, 1));
            rmax1 = fmaxf(rmax1, __shfl_xor_sync(0xffffffffu, rmax1, 2));
            float mn0 = fmaxf(m0, rmax0), mn1 = fmaxf(m1, rmax1);
            float sc0 = __expf(m0 - mn0), sc1 = __expf(m1 - mn1);
            m0 = mn0; m1 = mn1;
            float rs0 = 0.f, rs1 = 0.f;
#pragma unroll
            for (int nt = 0; nt < 8; nt++) {
#pragma unroll
                for (int e = 0; e < 4; e++) {
                    float p = __expf(acc[nt][e] - ((e < 2) ? mn0 : mn1));
                    acc[nt][e] = p;
                    if (e < 2) rs0 += p; else rs1 += p;
                }
            }
            rs0 += __shfl_xor_sync(0xffffffffu, rs0, 1);
            rs0 += __shfl_xor_sync(0xffffffffu, rs0, 2);
            rs1 += __shfl_xor_sync(0xffffffffu, rs1, 1);
            rs1 += __shfl_xor_sync(0xffffffffu, rs1, 2);
            l0 = l0 * sc0 + rs0;
            l1 = l1 * sc1 + rs1;
#pragma unroll
            for (int nt = 0; nt < 8; nt++) {
                O[nt][0] *= sc0; O[nt][1] *= sc0;
                O[nt][2] *= sc1; O[nt][3] *= sc1;
            }
        } else {
            // ---- gw: issue next-tile staging ----
            if (kt < 7) {
                const uint32_t kb2 = sb + SM_KV((kt + 1) % 3);
                for (int i = tidg; i < 512; i += 128) {
                    int row = i >> 3, c = i & 7;
                    size_t g = (size_t)(b * SEQ + k0t + 64 + row) * 1024 + h * 64 + c * 8;
                    uint32_t d = kb2 + (row * RS + c * 8) * 2;
                    cp_async16(d, g_xhi + g);
                    cp_async16(d + 9216, g_xlo + g);
                }
            }
            if (kt <= 5) {
                int pbase = base0 + 64 * (kt + 3);
                const uint32_t pb = sb + SM_POS((kt + 1) & 1);
                for (int i = tidg; i < 512; i += 128) {
                    int row = i >> 3, c = i & 7;
                    int j = pbase + row; if (j > 1023) j = 1023;
                    size_t g = (size_t)j * 64 + c * 8;
                    uint32_t d = pb + (row * RS + c * 8) * 2;
                    cp_async16(d, g_push + g);
                    cp_async16(d + 9216, g_posl + g);
                }
            }
            CP_COMMIT();
            if (kt < 7 && tidg < 64)
                mkb[((kt + 1) & 1) * 64 + tidg] = (float)mask[b * SEQ + k0t + 64 + tidg];
        }
        __syncthreads();   // B: combine done (Gs slot kt&1 free), K(kt) reads done

        // ================= window 2 =================
        if (is_main) {
            // P -> fp16 STS (own rows; same-warp LDSM later, barrier-covered)
#pragma unroll
            for (int nt = 0; nt < 8; nt++) {
                int c0 = nt * 8 + (lane & 3) * 2;
                __half2 p0 = __floats2half2_rn(acc[nt][0], acc[nt][1]);
                __half2 p1 = __floats2half2_rn(acc[nt][2], acc[nt][3]);
                *(uint32_t*)(smc + SM_PH + (rq0 * RS + c0) * 2) = *(uint32_t*)&p0;
                *(uint32_t*)(smc + SM_PH + (rq1 * RS + c0) * 2) = *(uint32_t*)&p1;
            }
            // issue V(kt) into KV(kt%3) hi half (K(kt) dead)
            {
                const uint32_t kb = sb + SM_KV(kt % 3);
                int row = tidg >> 1;
                int cbase = (tidg & 1) * 4;
#pragma unroll
                for (int cc = 0; cc < 4; cc++) {
                    size_t g = (size_t)(b * SEQ + k0t + row) * 1024 + h * 64 + (cbase + cc) * 8;
                    cp_async16(kb + (row * RS + (cbase + cc) * 8) * 2, g_vf16 + g);
                }
            }
            CP_COMMIT();
            CP_WAIT(0);     // publish V before sync C (cross-thread LDSM at kt+1)
        } else {
            CP_WAIT(1);     // retire all but the group issued this tile
            if (kt <= 6) g_block(sb, Gs, a1h, a1l, wg, lane, kt + 2, Eh, base0);
            CP_WAIT(0);     // publish K(kt+1)/pos(kt+3) before sync C
        }
        __syncthreads();   // C
    }

    if (is_main) {
        // ---- final PV(7) ----
        {
            const uint32_t vb = sb + SM_KV(7 % 3);
            int rowP = 16 * wg + (qd & 1) * 8 + lr;
#pragma unroll
            for (int ks = 0; ks < 4; ks++) {
                int colP = ks * 16 + (qd >> 1) * 8;
                uint32_t ap[4];
                ldmatrix_x4(ap, sb + SM_PH + (uint32_t)(rowP * RS + colP) * 2);
                int rowV = ks * 16 + (qd & 1) * 8 + lr;
#pragma unroll
                for (int dt = 0; dt < 4; dt++) {
                    int colV = dt * 16 + (qd >> 1) * 8;
                    uint32_t off = (uint32_t)(rowV * RS + colV) * 2;
                    uint32_t vh[4];
                    ldmatrix_x4_t(vh, vb + off);
                    mma_f16(O[dt * 2], ap, vh);
                    mma_f16(O[dt * 2 + 1], ap, vh + 2);
                }
            }
        }
        // ---- epilogue: out = O / l ----
        float li0 = 1.f / l0, li1 = 1.f / l1;
#pragma unroll
        for (int nt = 0; nt < 8; nt++) {
            int col = h * 64 + nt * 8 + (lane & 3) * 2;
            size_t r0o = (size_t)(b * SEQ + q0 + rq0) * DM + col;
            size_t r1o = (size_t)(b * SEQ + q0 + rq1) * DM + col;
            *(float2*)(out + r0o) = make_float2(O[nt][0] * li0, O[nt][1] * li0);
            *(float2*)(out + r1o) = make_float2(O[nt][2] * li1, O[nt][3] * li1);
        }
    }
}

// ---------------------------------------------------------------------------
extern "C" void kernel_launch(void* const* d_in, const int* in_sizes, int n_in,
                              void* d_out, int out_size) {
    const float* x   = (const float*)d_in[0];
    const int*   msk = (const int*)d_in[1];
    const float* Wqv = (const float*)d_in[2];
    const float* rr  = (const float*)d_in[3];
    const float* rw  = (const float*)d_in[4];
    float* out = (float*)d_out;

    cudaFuncSetAttribute(k_attn, cudaFuncAttributeMaxDynamicSharedMemorySize, SM_ATTN_TOT);
    cudaFuncSetAttribute(k_mm, cudaFuncAttributeMaxDynamicSharedMemorySize, 3 * STAGE_B);

    k_cvt_x<<<4096, 256>>>(x);
    k_cvt_w<<<dim3(64, 32), dim3(32, 8)>>>(Wqv);
    k_pos<<<256, 256>>>();
    k_E<<<dim3(8, 16), 128>>>(rr, rw);
    k_mm<<<dim3(16, 32), 256, 3 * STAGE_B>>>(rr);
    k_attn<<<dim3(8, 128), 256, SM_ATTN_TOT>>>(msk, out);
}